// round 11
// baseline (speedup 1.0000x reference)
#include <cuda_runtime.h>
#include <stdint.h>

// ---------------------------------------------------------------------------
// Problem constants
// ---------------------------------------------------------------------------
static const int kB  = 1024;   // batch
static const int kIN = 784;    // input dim
static const int kE  = 256;    // embed dim
static const int kC  = 10;     // classes
static const int kAD = 3;      // ADIM
static const int kBR = 4;      // BRAIN
static const int kNB = 64;     // blocks
static const int kJ  = 4;      // NJUMPS
static const int TS  = 16;     // samples per tile (weight-stream amortization)
static const int SP  = 20;     // interleaved activation row stride (16B-aligned)
static const int KOUT = kAD * kBR;  // 12
static const int GY  = 8;      // y-grid (tiles in flight per block)

// smem-staged weight pipeline (R8 discipline: 4-ring, 2-ahead, wait_group 2)
static const int CH   = 32;          // e-rows per chunk
static const int NCH  = kE / CH;     // 8 chunks per layer
static const int NBUF = 4;           // ring buffers
static const int WBUF = CH * kE;     // 8192 floats per buffer

// dynamic smem layout (floats)
static const int OFF_P0 = 0;                        // kE*SP = 5120
static const int OFF_P1 = kE * SP;                  // 5120
static const int OFF_W  = 2 * kE * SP;              // 10240 .. +32768
static const int OFF_T  = OFF_W + NBUF * WBUF;      // 43008 (TS*kE = 4096)
static const int OFF_W2 = OFF_T + TS * kE;          // 47104 (KOUT*kE = 3072)
static const int SMEM_FLOATS = OFF_W2 + KOUT * kE;  // 50176
static const int SMEM_BYTES  = SMEM_FLOATS * 4;     // 200704 (< 227KB cap)

// ---------------------------------------------------------------------------
// Scratch (device globals -- no cudaMalloc allowed)
// ---------------------------------------------------------------------------
__device__ float g_state[kB * kE];
__device__ float g_init [kB * kE];
__device__ int   g_done [kB];
__device__ int   g_cnt  [kJ + 1][kNB];
__device__ int   g_list [kJ + 1][kNB][kB];

// ---------------------------------------------------------------------------
// Threefry-2x32-20 (KAT: key(0,0) ctr(0,0) -> 0x6b200159, 0x99ba4efe)
// ---------------------------------------------------------------------------
__host__ __device__ inline void tf2x32(uint32_t k0, uint32_t k1,
                                       uint32_t x0, uint32_t x1,
                                       uint32_t* o0, uint32_t* o1)
{
    uint32_t ks2 = k0 ^ k1 ^ 0x1BD11BDAu;
    x0 += k0; x1 += k1;
#define TF_ROT(v, d) (((v) << (d)) | ((v) >> (32 - (d))))
#define TF_R4(a, b, c, d)                                    \
    { x0 += x1; x1 = TF_ROT(x1, a); x1 ^= x0;                \
      x0 += x1; x1 = TF_ROT(x1, b); x1 ^= x0;                \
      x0 += x1; x1 = TF_ROT(x1, c); x1 ^= x0;                \
      x0 += x1; x1 = TF_ROT(x1, d); x1 ^= x0; }
    TF_R4(13, 15, 26, 6)   x0 += k1;  x1 += ks2 + 1u;
    TF_R4(17, 29, 16, 24)  x0 += ks2; x1 += k0  + 2u;
    TF_R4(13, 15, 26, 6)   x0 += k0;  x1 += k1  + 3u;
    TF_R4(17, 29, 16, 24)  x0 += k1;  x1 += ks2 + 4u;
    TF_R4(13, 15, 26, 6)   x0 += ks2; x1 += k0  + 5u;
#undef TF_R4
#undef TF_ROT
    *o0 = x0; *o1 = x1;
}

// exact JAX gumbel (jax_threefry_partitionable): bits = o0^o1 of tf(key,(0,idx))
__device__ __forceinline__ float gumbel_exact(uint32_t k0, uint32_t k1, uint32_t idx)
{
    uint32_t y0, y1;
    tf2x32(k0, k1, 0u, idx, &y0, &y1);
    uint32_t bits = y0 ^ y1;
    float u = __uint_as_float((bits >> 9) | 0x3f800000u) - 1.0f;
    const float minv = 1e-6f;
    const float span = 0.999999f - 1e-6f;
    float vv = fmaxf(minv, u * span + minv);
    return (float)(-log(-log((double)vv)));  // fp64: immune to fast-math logf
}

// ---------------------------------------------------------------------------
// Packed f32x2 helpers
// ---------------------------------------------------------------------------
#define FMA2(acc, a, b) \
    asm("fma.rn.f32x2 %0, %1, %2, %0;" : "+l"(acc) : "l"(a), "l"(b))

__device__ __forceinline__ unsigned long long pack2(float lo, float hi)
{
    unsigned long long p;
    unsigned int l = __float_as_uint(lo), h = __float_as_uint(hi);
    asm("mov.b64 %0, {%1, %2};" : "=l"(p) : "r"(l), "r"(h));
    return p;
}
__device__ __forceinline__ void unpack2(unsigned long long p, float* lo, float* hi)
{
    unsigned int l, h;
    asm("mov.b64 {%0, %1}, %2;" : "=r"(l), "=r"(h) : "l"(p));
    *lo = __uint_as_float(l); *hi = __uint_as_float(h);
}

// ---------------------------------------------------------------------------
// cp.async helpers
// ---------------------------------------------------------------------------
__device__ __forceinline__ void cp16(float* s, const float* g)
{
    asm volatile("cp.async.cg.shared.global [%0], [%1], 16;"
                 :: "r"((uint32_t)__cvta_generic_to_shared(s)), "l"(g));
}
__device__ __forceinline__ void cp_commit() { asm volatile("cp.async.commit_group;"); }
__device__ __forceinline__ void cp_wait0()  { asm volatile("cp.async.wait_group 0;"); }
__device__ __forceinline__ void cp_wait1()  { asm volatile("cp.async.wait_group 1;"); }
__device__ __forceinline__ void cp_wait2()  { asm volatile("cp.async.wait_group 2;"); }

// issue chunk c of weight matrix gW ([kE][kE] row-major) into ring buffer c%NBUF
__device__ __forceinline__ void issue_chunk(float* sW, const float* gW, int c, int t)
{
    float* dst = sW + (size_t)(c % NBUF) * WBUF;
    const float* src = gW + (size_t)c * WBUF;
    #pragma unroll
    for (int k = 0; k < 8; k++)
        cp16(dst + (size_t)(t + k * 256) * 4, src + (size_t)(t + k * 256) * 4);
    cp_commit();
}

// ---------------------------------------------------------------------------
// One dense layer over 16 samples, weights 4-ring-buffered through smem:
//   acc pair p = samples (2p,2p+1):  acc += W[e][t] * in[e][s], e ascending
//   (per-sample scalar-FMA order identical to all prior passing rounds).
// sIn interleaved: value(e,s) = sIn[e*SP + s]. Caller synced sIn beforehand.
// WAR safety (R8): issue(c+2) into buf (c+2)%4; laggards compute c-1 on buf
// (c+3)%4; buf (c+2)%4 last read at c-2, fenced by barrier(c-1).
// ---------------------------------------------------------------------------
__device__ __forceinline__ void layer_smem(const float* sIn,
                                           const float* __restrict__ gW,
                                           float bv, float* sW, int t,
                                           unsigned long long* acc)
{
    #pragma unroll
    for (int p = 0; p < 8; p++) acc[p] = pack2(bv, bv);

    issue_chunk(sW, gW, 0, t);
    issue_chunk(sW, gW, 1, t);
    #pragma unroll 1
    for (int c = 0; c < NCH; c++) {
        if (c + 2 < NCH)      { issue_chunk(sW, gW, c + 2, t); cp_wait2(); }
        else if (c + 1 < NCH) { cp_wait1(); }
        else                  { cp_wait0(); }
        __syncthreads();
        const float* wb = sW + (size_t)(c % NBUF) * WBUF + t;
        const float* ab = sIn + (size_t)(c * CH) * SP;
        #pragma unroll
        for (int e = 0; e < CH; e++) {
            float w = wb[e * kE];
            unsigned long long wp = pack2(w, w);
            const ulonglong2 a01 = *(const ulonglong2*)(ab + e * SP);
            const ulonglong2 a23 = *(const ulonglong2*)(ab + e * SP + 4);
            const ulonglong2 a45 = *(const ulonglong2*)(ab + e * SP + 8);
            const ulonglong2 a67 = *(const ulonglong2*)(ab + e * SP + 12);
            FMA2(acc[0], a01.x, wp);
            FMA2(acc[1], a01.y, wp);
            FMA2(acc[2], a23.x, wp);
            FMA2(acc[3], a23.y, wp);
            FMA2(acc[4], a45.x, wp);
            FMA2(acc[5], a45.y, wp);
            FMA2(acc[6], a67.x, wp);
            FMA2(acc[7], a67.y, wp);
        }
    }
}

// unpack 8 accs into 16 floats
__device__ __forceinline__ void unpack16(const unsigned long long* acc, float* o)
{
    #pragma unroll
    for (int p = 0; p < 8; p++)
        unpack2(acc[p], &o[2 * p + 0], &o[2 * p + 1]);
}

// ---------------------------------------------------------------------------
// Embed GEMM: C = A[MxK] @ W[KxN] + bias, copy to C2. Also zeroes g_cnt.
// ---------------------------------------------------------------------------
__global__ void embed_kernel(const float* __restrict__ A,
                             const float* __restrict__ W,
                             const float* __restrict__ bias,
                             float* __restrict__ C,
                             float* __restrict__ C2,
                             int M, int K, int Nn)
{
    const int t = threadIdx.x;
    if (blockIdx.x == 0 && blockIdx.y == 0) {
        int* c = &g_cnt[0][0];
        for (int i = t; i < (kJ + 1) * kNB; i += 256) c[i] = 0;
    }
    __shared__ float As[16][33];
    __shared__ float Ws[16][64];
    const int tx = t & 15;
    const int ty = t >> 4;
    const int row0 = blockIdx.y * 32;
    const int col0 = blockIdx.x * 64;
    float acc[2][4] = {{0.f,0.f,0.f,0.f},{0.f,0.f,0.f,0.f}};

    for (int k0 = 0; k0 < K; k0 += 16) {
        if (t < 128) {
            int r  = t >> 2;
            int kk = (t & 3) * 4;
            float4 v = *(const float4*)(A + (size_t)(row0 + r) * K + k0 + kk);
            As[kk + 0][r] = v.x; As[kk + 1][r] = v.y;
            As[kk + 2][r] = v.z; As[kk + 3][r] = v.w;
        }
        {
            int kk = t >> 4;
            int c  = (t & 15) * 4;
            *(float4*)&Ws[kk][c] =
                *(const float4*)(W + (size_t)(k0 + kk) * Nn + col0 + c);
        }
        __syncthreads();
        #pragma unroll
        for (int kk = 0; kk < 16; kk++) {
            float a0 = As[kk][ty * 2 + 0];
            float a1 = As[kk][ty * 2 + 1];
            float4 b4 = *(const float4*)&Ws[kk][tx * 4];
            acc[0][0] = fmaf(a0, b4.x, acc[0][0]);
            acc[0][1] = fmaf(a0, b4.y, acc[0][1]);
            acc[0][2] = fmaf(a0, b4.z, acc[0][2]);
            acc[0][3] = fmaf(a0, b4.w, acc[0][3]);
            acc[1][0] = fmaf(a1, b4.x, acc[1][0]);
            acc[1][1] = fmaf(a1, b4.y, acc[1][1]);
            acc[1][2] = fmaf(a1, b4.z, acc[1][2]);
            acc[1][3] = fmaf(a1, b4.w, acc[1][3]);
        }
        __syncthreads();
    }

    float4 bv = *(const float4*)(bias + col0 + tx * 4);
    #pragma unroll
    for (int i = 0; i < 2; i++) {
        float4 o;
        o.x = acc[i][0] + bv.x; o.y = acc[i][1] + bv.y;
        o.z = acc[i][2] + bv.z; o.w = acc[i][3] + bv.w;
        size_t off = (size_t)(row0 + ty * 2 + i) * Nn + col0 + tx * 4;
        *(float4*)(C + off)  = o;
        *(float4*)(C2 + off) = o;
    }
}

// ---------------------------------------------------------------------------
// Shared epilogue: logits + gumbel + argmax for one sample per warp.
// Returns routed block index in lane 0 (undefined elsewhere).
// ---------------------------------------------------------------------------
__device__ __forceinline__ int addr_head(const float* sT, const float* sW2T,
                                         const float* __restrict__ ab2,
                                         int s, int lane, int b,
                                         uint32_t k0, uint32_t k1)
{
    const unsigned fm = 0xffffffffu;
    float hr[kE / 32];
    #pragma unroll
    for (int q = 0; q < kE / 32; q++)
        hr[q] = sT[(size_t)s * kE + lane + 32 * q];
    float zmine = 0.f;
    #pragma unroll
    for (int k = 0; k < KOUT; k++) {
        float sum = 0.f;
        #pragma unroll
        for (int q = 0; q < kE / 32; q++)
            sum = fmaf(hr[q], sW2T[(size_t)k * kE + lane + 32 * q], sum);
        #pragma unroll
        for (int o = 16; o; o >>= 1) sum += __shfl_down_sync(fm, sum, o);
        float v = __shfl_sync(fm, sum, 0);
        if (lane == k) zmine = v + ab2[k];
    }
    if (lane < KOUT) zmine += gumbel_exact(k0, k1, (uint32_t)(b * KOUT + lane));
    float zv[KOUT];
    #pragma unroll
    for (int k = 0; k < KOUT; k++) zv[k] = __shfl_sync(fm, zmine, k);

    int n_val = 0;
    if (lane == 0) {
        #pragma unroll
        for (int d = 0; d < kAD; d++) {
            int bi = 0; float bvv = zv[d * kBR];
            #pragma unroll
            for (int c = 1; c < kBR; c++) {
                float x = zv[d * kBR + c];
                if (x > bvv) { bvv = x; bi = c; }
            }
            n_val = n_val * kBR + bi;
        }
    }
    return n_val;
}

// ---------------------------------------------------------------------------
// addr0: h = relu(state @ aW1 + ab1); logits (+gumbel key0); route list[0].
// 64 CTAs x 256 threads, 16 samples each.
// ---------------------------------------------------------------------------
__global__ void addr0_kernel(const float* __restrict__ aW1,
                             const float* __restrict__ ab1,
                             const float* __restrict__ aW2,
                             const float* __restrict__ ab2,
                             uint32_t k0, uint32_t k1)
{
    extern __shared__ float sm[];
    float* sP0  = sm + OFF_P0;
    float* sW   = sm + OFF_W;
    float* sT   = sm + OFF_T;
    float* sW2T = sm + OFF_W2;
    const int t = threadIdx.x, wid = t >> 5, lane = t & 31;
    const int b0 = blockIdx.x * TS;

    for (int i = t; i < kE * KOUT; i += 256)
        sW2T[(size_t)(i % KOUT) * kE + (i / KOUT)] = aW2[i];
    #pragma unroll
    for (int s = 0; s < TS; s++)
        sP0[t * SP + s] = g_state[(size_t)(b0 + s) * kE + t];
    __syncthreads();

    {
        unsigned long long acc[8];
        layer_smem(sP0, aW1, ab1[t], sW, t, acc);
        float o[TS];
        unpack16(acc, o);
        #pragma unroll
        for (int s = 0; s < TS; s++)
            sT[(size_t)s * kE + t] = fmaxf(o[s], 0.f);
    }
    __syncthreads();

    #pragma unroll
    for (int pass = 0; pass < 2; pass++) {
        const int s = wid + 8 * pass;
        const int b = b0 + s;
        int n_val = addr_head(sT, sW2T, ab2, s, lane, b, k0, k1);
        if (lane == 0) {
            g_done[b] = 0;
            int pos = atomicAdd(&g_cnt[0][n_val], 1);
            g_list[0][n_val][pos] = b;
        }
    }
}

// ---------------------------------------------------------------------------
// Fused jump: consume list[jin] grouped by block n = blockIdx.x, 16/tile.
// ---------------------------------------------------------------------------
__global__ void jump_kernel(const float* __restrict__ W1,
                            const float* __restrict__ b1,
                            const float* __restrict__ W2,
                            const float* __restrict__ b2,
                            const float* __restrict__ aW1,
                            const float* __restrict__ ab1,
                            const float* __restrict__ aW2,
                            const float* __restrict__ ab2,
                            uint32_t k0, uint32_t k1, int jin, int jout)
{
    const int n = blockIdx.x;
    const int cnt = g_cnt[jin][n];
    if ((int)(blockIdx.y * TS) >= cnt) return;

    extern __shared__ float sm[];
    float* sP0  = sm + OFF_P0;
    float* sP1  = sm + OFF_P1;
    float* sW   = sm + OFF_W;
    float* sT   = sm + OFF_T;
    float* sW2T = sm + OFF_W2;
    __shared__ float snorm[TS];
    __shared__ int   sids[TS];
    __shared__ int   sdone[TS];
    const int t = threadIdx.x, wid = t >> 5, lane = t & 31;
    const unsigned fm = 0xffffffffu;
    const float* bW1 = W1 + (size_t)n * kE * kE;
    const float* bW2 = W2 + (size_t)n * kE * kE;

    for (int i = t; i < kE * KOUT; i += 256)
        sW2T[(size_t)(i % KOUT) * kE + (i / KOUT)] = aW2[i];

    for (int tile = blockIdx.y; tile * TS < cnt; tile += gridDim.y) {
        const int m = min(TS, cnt - tile * TS);
        if (t < TS) {
            int id = (t < m) ? g_list[jin][n][tile * TS + t] : -1;
            sids[t]  = id;
            sdone[t] = (id >= 0) ? g_done[id] : 1;
        }
        __syncthreads();
        #pragma unroll
        for (int s = 0; s < TS; s++)
            sP0[t * SP + s] = (s < m) ? g_state[(size_t)sids[s] * kE + t] : 0.f;
        __syncthreads();
        {   // norms: warp wid -> samples wid, wid+8
            #pragma unroll
            for (int pass = 0; pass < 2; pass++) {
                const int s = wid + 8 * pass;
                float v = 0.f;
                #pragma unroll
                for (int q = 0; q < kE / 32; q++) {
                    float x = sP0[(lane + 32 * q) * SP + s];
                    v = fmaf(x, x, v);
                }
                #pragma unroll
                for (int o = 16; o; o >>= 1) v += __shfl_down_sync(fm, v, o);
                if (lane == 0) snorm[s] = sqrtf(v) + 1e-6f;
            }
        }
        __syncthreads();
        {   // layer 1: sP0 -> relu -> sP1
            unsigned long long acc[8];
            layer_smem(sP0, bW1, b1[n * kE + t], sW, t, acc);
            float o[TS];
            unpack16(acc, o);
            #pragma unroll
            for (int s = 0; s < TS; s++)
                sP1[t * SP + s] = fmaxf(o[s], 0.f);
        }
        __syncthreads();
        {   // layer 2: sP1 -> relu/norm -> sP0 (+ commit g_state if active)
            unsigned long long acc[8];
            layer_smem(sP1, bW2, b2[n * kE + t], sW, t, acc);
            float o[TS];
            unpack16(acc, o);
            #pragma unroll
            for (int s = 0; s < TS; s++) {
                float val = fmaxf(o[s], 0.f) / snorm[s];
                sP0[t * SP + s] = val;
                if (s < m && !sdone[s])
                    g_state[(size_t)sids[s] * kE + t] = val;
            }
        }
        __syncthreads();
        {   // layer 3: address hidden, sP0 -> relu -> sT (transposed)
            unsigned long long acc[8];
            layer_smem(sP0, aW1, ab1[t], sW, t, acc);
            float o[TS];
            unpack16(acc, o);
            #pragma unroll
            for (int s = 0; s < TS; s++)
                sT[(size_t)s * kE + t] = fmaxf(o[s], 0.f);
        }
        __syncthreads();

        #pragma unroll
        for (int pass = 0; pass < 2; pass++) {
            const int s = wid + 8 * pass;
            if (s < m) {
                const int b = sids[s];
                int n_val = addr_head(sT, sW2T, ab2, s, lane, b, k0, k1);
                if (lane == 0) {
                    int done_pre = sdone[s];
                    int rn = done_pre ? n : n_val;  // frozen keep block n
                    if (!done_pre && n_val == 0) g_done[b] = 1;
                    int pos = atomicAdd(&g_cnt[jout][rn], 1);
                    g_list[jout][rn][pos] = b;
                }
            }
        }
        __syncthreads();
    }
}

// ---------------------------------------------------------------------------
// Fused final: block MLP + /norm + initial_state residual + out hidden + head.
// ---------------------------------------------------------------------------
__global__ void final_kernel(const float* __restrict__ W1,
                             const float* __restrict__ b1,
                             const float* __restrict__ W2,
                             const float* __restrict__ b2,
                             const float* __restrict__ oW1,
                             const float* __restrict__ ob1,
                             const float* __restrict__ oW2,
                             const float* __restrict__ ob2,
                             float* __restrict__ outp)
{
    const int n = blockIdx.x;
    const int cnt = g_cnt[kJ][n];
    if ((int)(blockIdx.y * TS) >= cnt) return;

    extern __shared__ float sm[];
    float* sP0  = sm + OFF_P0;
    float* sP1  = sm + OFF_P1;
    float* sW   = sm + OFF_W;
    float* sT   = sm + OFF_T;
    float* sW2T = sm + OFF_W2;   // [kC][kE]
    __shared__ float snorm[TS];
    __shared__ int   sids[TS];
    const int t = threadIdx.x, wid = t >> 5, lane = t & 31;
    const unsigned fm = 0xffffffffu;
    const float* bW1 = W1 + (size_t)n * kE * kE;
    const float* bW2 = W2 + (size_t)n * kE * kE;

    for (int i = t; i < kE * kC; i += 256)
        sW2T[(size_t)(i % kC) * kE + (i / kC)] = oW2[i];

    for (int tile = blockIdx.y; tile * TS < cnt; tile += gridDim.y) {
        const int m = min(TS, cnt - tile * TS);
        if (t < TS) sids[t] = (t < m) ? g_list[kJ][n][tile * TS + t] : -1;
        __syncthreads();
        #pragma unroll
        for (int s = 0; s < TS; s++)
            sP0[t * SP + s] = (s < m) ? g_state[(size_t)sids[s] * kE + t] : 0.f;
        __syncthreads();
        {
            #pragma unroll
            for (int pass = 0; pass < 2; pass++) {
                const int s = wid + 8 * pass;
                float v = 0.f;
                #pragma unroll
                for (int q = 0; q < kE / 32; q++) {
                    float x = sP0[(lane + 32 * q) * SP + s];
                    v = fmaf(x, x, v);
                }
                #pragma unroll
                for (int o = 16; o; o >>= 1) v += __shfl_down_sync(fm, v, o);
                if (lane == 0) snorm[s] = sqrtf(v) + 1e-6f;
            }
        }
        __syncthreads();
        {   // layer 1
            unsigned long long acc[8];
            layer_smem(sP0, bW1, b1[n * kE + t], sW, t, acc);
            float o[TS];
            unpack16(acc, o);
            #pragma unroll
            for (int s = 0; s < TS; s++)
                sP1[t * SP + s] = fmaxf(o[s], 0.f);
        }
        __syncthreads();
        {   // layer 2 + /norm + residual -> sP0
            unsigned long long acc[8];
            layer_smem(sP1, bW2, b2[n * kE + t], sW, t, acc);
            float o[TS];
            unpack16(acc, o);
            #pragma unroll
            for (int s = 0; s < TS; s++) {
                float val = fmaxf(o[s], 0.f) / snorm[s];
                if (s < m) val += g_init[(size_t)sids[s] * kE + t];
                sP0[t * SP + s] = val;
            }
        }
        __syncthreads();
        {   // out hidden -> sT
            unsigned long long acc[8];
            layer_smem(sP0, oW1, ob1[t], sW, t, acc);
            float o[TS];
            unpack16(acc, o);
            #pragma unroll
            for (int s = 0; s < TS; s++)
                sT[(size_t)s * kE + t] = fmaxf(o[s], 0.f);
        }
        __syncthreads();

        #pragma unroll
        for (int pass = 0; pass < 2; pass++) {
            const int s = wid + 8 * pass;
            if (s < m) {
                const int b = sids[s];
                float hr[kE / 32];
                #pragma unroll
                for (int q = 0; q < kE / 32; q++)
                    hr[q] = sT[(size_t)s * kE + lane + 32 * q];
                #pragma unroll
                for (int c = 0; c < kC; c++) {
                    float sum = 0.f;
                    #pragma unroll
                    for (int q = 0; q < kE / 32; q++)
                        sum = fmaf(hr[q], sW2T[(size_t)c * kE + lane + 32 * q], sum);
                    #pragma unroll
                    for (int o = 16; o; o >>= 1) sum += __shfl_down_sync(fm, sum, o);
                    if (lane == 0) outp[(size_t)b * kC + c] = sum + ob2[c];
                }
            }
        }
        __syncthreads();
    }
}

// ---------------------------------------------------------------------------
// Launch: 7 kernels total
// ---------------------------------------------------------------------------
extern "C" void kernel_launch(void* const* d_in, const int* in_sizes, int n_in,
                              void* d_out, int out_size)
{
    (void)in_sizes; (void)n_in; (void)out_size;
    const float* x      = (const float*)d_in[0];
    const float* W_emb  = (const float*)d_in[1];
    const float* b_emb  = (const float*)d_in[2];
    const float* st_W1  = (const float*)d_in[3];
    const float* st_b1  = (const float*)d_in[4];
    const float* st_W2  = (const float*)d_in[5];
    const float* st_b2  = (const float*)d_in[6];
    const float* at0_W1 = (const float*)d_in[7];
    const float* at0_b1 = (const float*)d_in[8];
    const float* at0_W2 = (const float*)d_in[9];
    const float* at0_b2 = (const float*)d_in[10];
    const float* out_W1 = (const float*)d_in[11];
    const float* out_b1 = (const float*)d_in[12];
    const float* out_W2 = (const float*)d_in[13];
    const float* out_b2 = (const float*)d_in[14];
    float* out = (float*)d_out;

    // JAX keys: key_j = threefry((0,42), (0,j))  [fold_in(_GKEY, j)]
    uint32_t kk0[kJ + 1], kk1[kJ + 1];
    for (int j = 0; j <= kJ; j++)
        tf2x32(0u, 42u, 0u, (uint32_t)j, &kk0[j], &kk1[j]);

    float *p_state, *p_init;
    cudaGetSymbolAddress((void**)&p_state, g_state);
    cudaGetSymbolAddress((void**)&p_init,  g_init);

    cudaFuncSetAttribute(addr0_kernel,
        cudaFuncAttributeMaxDynamicSharedMemorySize, SMEM_BYTES);
    cudaFuncSetAttribute(jump_kernel,
        cudaFuncAttributeMaxDynamicSharedMemorySize, SMEM_BYTES);
    cudaFuncSetAttribute(final_kernel,
        cudaFuncAttributeMaxDynamicSharedMemorySize, SMEM_BYTES);

    // 1. embed (also zeroes routing counters for this replay)
    embed_kernel<<<dim3(kE / 64, kB / 32), 256>>>(x, W_emb, b_emb,
                                                  p_state, p_init, kB, kIN, kE);
    // 2. initial address
    addr0_kernel<<<kB / TS, 256, SMEM_BYTES>>>(at0_W1, at0_b1, at0_W2, at0_b2,
                                               kk0[0], kk1[0]);
    // 3-6. fused jumps
    for (int i = 0; i < kJ; i++)
        jump_kernel<<<dim3(kNB, GY), 256, SMEM_BYTES>>>(
            st_W1, st_b1, st_W2, st_b2,
            at0_W1, at0_b1, at0_W2, at0_b2,
            kk0[i + 1], kk1[i + 1], i, i + 1);
    // 7. fused final block step + output head
    final_kernel<<<dim3(kNB, GY), 256, SMEM_BYTES>>>(
        st_W1, st_b1, st_W2, st_b2,
        out_W1, out_b1, out_W2, out_b2, out);
}

// round 12
// speedup vs baseline: 1.6083x; 1.6083x over previous
#include <cuda_runtime.h>
#include <stdint.h>

// ---------------------------------------------------------------------------
// Problem constants
// ---------------------------------------------------------------------------
static const int kB  = 1024;   // batch
static const int kIN = 784;    // input dim
static const int kE  = 256;    // embed dim
static const int kC  = 10;     // classes
static const int kAD = 3;      // ADIM
static const int kBR = 4;      // BRAIN
static const int kNB = 64;     // blocks
static const int kJ  = 4;      // NJUMPS
static const int TS  = 8;      // samples per tile (R8 config)
static const int SP  = 12;     // interleaved activation row stride
static const int KOUT = kAD * kBR;  // 12

// TMA-staged weight pipeline: ring of 4 x 32KB buffers, 2 ahead
static const int CH   = 32;          // e-rows per chunk
static const int NCH  = kE / CH;     // 8 chunks per layer
static const int NBUF = 4;           // ring buffers
static const int WBUF = CH * kE;     // 8192 floats per buffer
static const int WBYTES = WBUF * 4;  // 32768 bytes

// dynamic smem layout (floats)
static const int OFF_P0 = 0;                        // 3072
static const int OFF_P1 = kE * SP;                  // 3072
static const int OFF_W  = 2 * kE * SP;              // 6144 .. +32768 floats
static const int OFF_T  = OFF_W + NBUF * WBUF;      // 38912 (TS*kE)
static const int OFF_W2 = OFF_T + TS * kE;          // 40960 (KOUT*kE)
static const int OFF_MB = OFF_W2 + KOUT * kE;       // 44032 (mbarriers, 4x2)
static const int SMEM_FLOATS = OFF_MB + 16;         // 44048
static const int SMEM_BYTES  = SMEM_FLOATS * 4;     // 176192

// ---------------------------------------------------------------------------
// Scratch (device globals -- no cudaMalloc allowed)
// ---------------------------------------------------------------------------
__device__ float g_state[kB * kE];
__device__ float g_init [kB * kE];
__device__ int   g_done [kB];
__device__ int   g_cnt  [kJ + 1][kNB];
__device__ int   g_list [kJ + 1][kNB][kB];

// ---------------------------------------------------------------------------
// Threefry-2x32-20 (KAT: key(0,0) ctr(0,0) -> 0x6b200159, 0x99ba4efe)
// ---------------------------------------------------------------------------
__host__ __device__ inline void tf2x32(uint32_t k0, uint32_t k1,
                                       uint32_t x0, uint32_t x1,
                                       uint32_t* o0, uint32_t* o1)
{
    uint32_t ks2 = k0 ^ k1 ^ 0x1BD11BDAu;
    x0 += k0; x1 += k1;
#define TF_ROT(v, d) (((v) << (d)) | ((v) >> (32 - (d))))
#define TF_R4(a, b, c, d)                                    \
    { x0 += x1; x1 = TF_ROT(x1, a); x1 ^= x0;                \
      x0 += x1; x1 = TF_ROT(x1, b); x1 ^= x0;                \
      x0 += x1; x1 = TF_ROT(x1, c); x1 ^= x0;                \
      x0 += x1; x1 = TF_ROT(x1, d); x1 ^= x0; }
    TF_R4(13, 15, 26, 6)   x0 += k1;  x1 += ks2 + 1u;
    TF_R4(17, 29, 16, 24)  x0 += ks2; x1 += k0  + 2u;
    TF_R4(13, 15, 26, 6)   x0 += k0;  x1 += k1  + 3u;
    TF_R4(17, 29, 16, 24)  x0 += k1;  x1 += ks2 + 4u;
    TF_R4(13, 15, 26, 6)   x0 += ks2; x1 += k0  + 5u;
#undef TF_R4
#undef TF_ROT
    *o0 = x0; *o1 = x1;
}

// exact JAX gumbel (jax_threefry_partitionable): bits = o0^o1 of tf(key,(0,idx))
__device__ __forceinline__ float gumbel_exact(uint32_t k0, uint32_t k1, uint32_t idx)
{
    uint32_t y0, y1;
    tf2x32(k0, k1, 0u, idx, &y0, &y1);
    uint32_t bits = y0 ^ y1;
    float u = __uint_as_float((bits >> 9) | 0x3f800000u) - 1.0f;
    const float minv = 1e-6f;
    const float span = 0.999999f - 1e-6f;
    float vv = fmaxf(minv, u * span + minv);
    return (float)(-log(-log((double)vv)));  // fp64: immune to fast-math logf
}

// ---------------------------------------------------------------------------
// Packed f32x2 helpers
// ---------------------------------------------------------------------------
#define FMA2(acc, a, b) \
    asm("fma.rn.f32x2 %0, %1, %2, %0;" : "+l"(acc) : "l"(a), "l"(b))

__device__ __forceinline__ unsigned long long pack2(float lo, float hi)
{
    unsigned long long p;
    unsigned int l = __float_as_uint(lo), h = __float_as_uint(hi);
    asm("mov.b64 %0, {%1, %2};" : "=l"(p) : "r"(l), "r"(h));
    return p;
}
__device__ __forceinline__ void unpack2(unsigned long long p, float* lo, float* hi)
{
    unsigned int l, h;
    asm("mov.b64 {%0, %1}, %2;" : "=r"(l), "=r"(h) : "l"(p));
    *lo = __uint_as_float(l); *hi = __uint_as_float(h);
}

// ---------------------------------------------------------------------------
// TMA bulk + mbarrier helpers
// ---------------------------------------------------------------------------
__device__ __forceinline__ uint32_t smem_u32(const void* p)
{
    return (uint32_t)__cvta_generic_to_shared(p);
}

__device__ __forceinline__ void mbar_init(uint32_t mbar, uint32_t count)
{
    asm volatile("mbarrier.init.shared.b64 [%0], %1;"
                 :: "r"(mbar), "r"(count) : "memory");
}

__device__ __forceinline__ void mbar_expect_tx(uint32_t mbar, uint32_t bytes)
{
    asm volatile("mbarrier.arrive.expect_tx.shared.b64 _, [%0], %1;"
                 :: "r"(mbar), "r"(bytes) : "memory");
}

__device__ __forceinline__ void mbar_wait(uint32_t mbar, uint32_t parity)
{
    asm volatile(
        "{\n\t"
        ".reg .pred P1;\n\t"
        "WAIT_LOOP_%=:\n\t"
        "mbarrier.try_wait.parity.acquire.cta.shared::cta.b64 P1, [%0], %1, 0x989680;\n\t"
        "@P1 bra.uni WAIT_DONE_%=;\n\t"
        "bra.uni WAIT_LOOP_%=;\n\t"
        "WAIT_DONE_%=:\n\t"
        "}"
        :: "r"(mbar), "r"(parity) : "memory");
}

__device__ __forceinline__ void tma_bulk(uint32_t dst_smem, const float* gsrc,
                                         uint32_t bytes, uint32_t mbar)
{
    asm volatile(
        "cp.async.bulk.shared::cluster.global.mbarrier::complete_tx::bytes "
        "[%0], [%1], %2, [%3];"
        :: "r"(dst_smem), "l"(gsrc), "r"(bytes), "r"(mbar) : "memory");
}

// issue chunk idx (global counter) of weights gWbase+((idx%NCH per layer handled
// by caller passing per-layer base)) -- caller passes exact src pointer
__device__ __forceinline__ void issue_chunk_tma(float* sW, uint32_t mb_base,
                                                const float* gW, int local_c,
                                                int idx, int tid)
{
    if (tid == 0) {
        uint32_t mbar = mb_base + (uint32_t)(idx & 3) * 8;
        uint32_t dst  = smem_u32(sW + (size_t)(idx & 3) * WBUF);
        mbar_expect_tx(mbar, WBYTES);
        tma_bulk(dst, gW + (size_t)local_c * WBUF, WBYTES, mbar);
    }
}

// ---------------------------------------------------------------------------
// One dense layer, weights TMA-bulk staged through a 4-ring:
//   acc pair p = samples (2p,2p+1): acc += W[e][t]*in[e][s], e ascending
//   (identical scalar-FMA order to all passing rounds -> bit-identical).
// ck: running chunk counter (uniform across threads; advanced by NCH).
// WAR safety: issue(c+2) happens after the barrier that proves all threads
// finished compute(c-2), which was the last reader of buffer (c+2)%4.
// ---------------------------------------------------------------------------
__device__ __forceinline__ void layer_tma(const float* sIn,
                                          const float* __restrict__ gW,
                                          float bv, float* sW, uint32_t mb_base,
                                          int t, int& ck,
                                          unsigned long long* acc)
{
    #pragma unroll
    for (int p = 0; p < 4; p++) acc[p] = pack2(bv, bv);

    issue_chunk_tma(sW, mb_base, gW, 0, ck + 0, t);
    issue_chunk_tma(sW, mb_base, gW, 1, ck + 1, t);
    #pragma unroll 1
    for (int c = 0; c < NCH; c++) {
        __syncthreads();            // all threads finished compute(c-1)
        if (c + 2 < NCH)
            issue_chunk_tma(sW, mb_base, gW, c + 2, ck + c + 2, t);
        {   // wait for chunk c data
            int idx = ck + c;
            mbar_wait(mb_base + (uint32_t)(idx & 3) * 8,
                      (uint32_t)((idx >> 2) & 1));
        }
        const float* wb = sW + (size_t)((ck + c) & 3) * WBUF + t;
        const float* ab = sIn + (size_t)(c * CH) * SP;
        #pragma unroll
        for (int e = 0; e < CH; e++) {
            float w = wb[e * kE];
            unsigned long long wp = pack2(w, w);
            ulonglong2 a01 = *(const ulonglong2*)(ab + e * SP);
            ulonglong2 a23 = *(const ulonglong2*)(ab + e * SP + 4);
            FMA2(acc[0], a01.x, wp);
            FMA2(acc[1], a01.y, wp);
            FMA2(acc[2], a23.x, wp);
            FMA2(acc[3], a23.y, wp);
        }
    }
    ck += NCH;
}

// ---------------------------------------------------------------------------
// Embed GEMM: C = A[MxK] @ W[KxN] + bias, copy to C2. Also zeroes g_cnt.
// ---------------------------------------------------------------------------
__global__ void embed_kernel(const float* __restrict__ A,
                             const float* __restrict__ W,
                             const float* __restrict__ bias,
                             float* __restrict__ C,
                             float* __restrict__ C2,
                             int M, int K, int Nn)
{
    const int t = threadIdx.x;
    if (blockIdx.x == 0 && blockIdx.y == 0) {
        int* c = &g_cnt[0][0];
        for (int i = t; i < (kJ + 1) * kNB; i += 256) c[i] = 0;
    }
    __shared__ float As[16][33];
    __shared__ float Ws[16][64];
    const int tx = t & 15;
    const int ty = t >> 4;
    const int row0 = blockIdx.y * 32;
    const int col0 = blockIdx.x * 64;
    float acc[2][4] = {{0.f,0.f,0.f,0.f},{0.f,0.f,0.f,0.f}};

    for (int k0 = 0; k0 < K; k0 += 16) {
        if (t < 128) {
            int r  = t >> 2;
            int kk = (t & 3) * 4;
            float4 v = *(const float4*)(A + (size_t)(row0 + r) * K + k0 + kk);
            As[kk + 0][r] = v.x; As[kk + 1][r] = v.y;
            As[kk + 2][r] = v.z; As[kk + 3][r] = v.w;
        }
        {
            int kk = t >> 4;
            int c  = (t & 15) * 4;
            *(float4*)&Ws[kk][c] =
                *(const float4*)(W + (size_t)(k0 + kk) * Nn + col0 + c);
        }
        __syncthreads();
        #pragma unroll
        for (int kk = 0; kk < 16; kk++) {
            float a0 = As[kk][ty * 2 + 0];
            float a1 = As[kk][ty * 2 + 1];
            float4 b4 = *(const float4*)&Ws[kk][tx * 4];
            acc[0][0] = fmaf(a0, b4.x, acc[0][0]);
            acc[0][1] = fmaf(a0, b4.y, acc[0][1]);
            acc[0][2] = fmaf(a0, b4.z, acc[0][2]);
            acc[0][3] = fmaf(a0, b4.w, acc[0][3]);
            acc[1][0] = fmaf(a1, b4.x, acc[1][0]);
            acc[1][1] = fmaf(a1, b4.y, acc[1][1]);
            acc[1][2] = fmaf(a1, b4.z, acc[1][2]);
            acc[1][3] = fmaf(a1, b4.w, acc[1][3]);
        }
        __syncthreads();
    }

    float4 bv = *(const float4*)(bias + col0 + tx * 4);
    #pragma unroll
    for (int i = 0; i < 2; i++) {
        float4 o;
        o.x = acc[i][0] + bv.x; o.y = acc[i][1] + bv.y;
        o.z = acc[i][2] + bv.z; o.w = acc[i][3] + bv.w;
        size_t off = (size_t)(row0 + ty * 2 + i) * Nn + col0 + tx * 4;
        *(float4*)(C + off)  = o;
        *(float4*)(C2 + off) = o;
    }
}

// ---------------------------------------------------------------------------
// Shared epilogue: logits + gumbel + argmax for one sample per warp.
// ---------------------------------------------------------------------------
__device__ __forceinline__ int addr_head(const float* sT, const float* sW2T,
                                         const float* __restrict__ ab2,
                                         int wid, int lane, int b,
                                         uint32_t k0, uint32_t k1)
{
    const unsigned fm = 0xffffffffu;
    float hr[kE / 32];
    #pragma unroll
    for (int q = 0; q < kE / 32; q++)
        hr[q] = sT[(size_t)wid * kE + lane + 32 * q];
    float zmine = 0.f;
    #pragma unroll
    for (int k = 0; k < KOUT; k++) {
        float sum = 0.f;
        #pragma unroll
        for (int q = 0; q < kE / 32; q++)
            sum = fmaf(hr[q], sW2T[(size_t)k * kE + lane + 32 * q], sum);
        #pragma unroll
        for (int o = 16; o; o >>= 1) sum += __shfl_down_sync(fm, sum, o);
        float v = __shfl_sync(fm, sum, 0);
        if (lane == k) zmine = v + ab2[k];
    }
    if (lane < KOUT) zmine += gumbel_exact(k0, k1, (uint32_t)(b * KOUT + lane));
    float zv[KOUT];
    #pragma unroll
    for (int k = 0; k < KOUT; k++) zv[k] = __shfl_sync(fm, zmine, k);

    int n_val = 0;
    if (lane == 0) {
        #pragma unroll
        for (int d = 0; d < kAD; d++) {
            int bi = 0; float bvv = zv[d * kBR];
            #pragma unroll
            for (int c = 1; c < kBR; c++) {
                float x = zv[d * kBR + c];
                if (x > bvv) { bvv = x; bi = c; }
            }
            n_val = n_val * kBR + bi;
        }
    }
    return n_val;
}

// ---------------------------------------------------------------------------
// addr0: h = relu(state @ aW1 + ab1); logits (+gumbel key0); route list[0].
// ---------------------------------------------------------------------------
__global__ void addr0_kernel(const float* __restrict__ aW1,
                             const float* __restrict__ ab1,
                             const float* __restrict__ aW2,
                             const float* __restrict__ ab2,
                             uint32_t k0, uint32_t k1)
{
    extern __shared__ float sm[];
    float* sP0  = sm + OFF_P0;
    float* sW   = sm + OFF_W;
    float* sT   = sm + OFF_T;
    float* sW2T = sm + OFF_W2;
    const uint32_t mb_base = smem_u32(sm + OFF_MB);
    const int t = threadIdx.x, wid = t >> 5, lane = t & 31;
    const int b0 = blockIdx.x * TS;
    int ck = 0;

    if (t == 0)
        for (int b = 0; b < NBUF; b++) mbar_init(mb_base + b * 8, 1);
    for (int i = t; i < kE * KOUT; i += 256)
        sW2T[(size_t)(i % KOUT) * kE + (i / KOUT)] = aW2[i];
    #pragma unroll
    for (int s = 0; s < TS; s++)
        sP0[t * SP + s] = g_state[(size_t)(b0 + s) * kE + t];
    __syncthreads();

    {
        unsigned long long acc[4];
        layer_tma(sP0, aW1, ab1[t], sW, mb_base, t, ck, acc);
        #pragma unroll
        for (int p = 0; p < 4; p++) {
            float lo, hi; unpack2(acc[p], &lo, &hi);
            sT[(size_t)(2 * p + 0) * kE + t] = fmaxf(lo, 0.f);
            sT[(size_t)(2 * p + 1) * kE + t] = fmaxf(hi, 0.f);
        }
    }
    __syncthreads();

    const int b = b0 + wid;
    int n_val = addr_head(sT, sW2T, ab2, wid, lane, b, k0, k1);
    if (lane == 0) {
        g_done[b] = 0;
        int pos = atomicAdd(&g_cnt[0][n_val], 1);
        g_list[0][n_val][pos] = b;
    }
}

// ---------------------------------------------------------------------------
// Fused jump (TMA weight ring): consume list[jin], block n = blockIdx.x.
// ---------------------------------------------------------------------------
__global__ void jump_kernel(const float* __restrict__ W1,
                            const float* __restrict__ b1,
                            const float* __restrict__ W2,
                            const float* __restrict__ b2,
                            const float* __restrict__ aW1,
                            const float* __restrict__ ab1,
                            const float* __restrict__ aW2,
                            const float* __restrict__ ab2,
                            uint32_t k0, uint32_t k1, int jin, int jout)
{
    const int n = blockIdx.x;
    const int cnt = g_cnt[jin][n];
    if ((int)(blockIdx.y * TS) >= cnt) return;

    extern __shared__ float sm[];
    float* sP0  = sm + OFF_P0;
    float* sP1  = sm + OFF_P1;
    float* sW   = sm + OFF_W;
    float* sT   = sm + OFF_T;
    float* sW2T = sm + OFF_W2;
    const uint32_t mb_base = smem_u32(sm + OFF_MB);
    __shared__ float snorm[TS];
    __shared__ int   sids[TS];
    __shared__ int   sdone[TS];
    const int t = threadIdx.x, wid = t >> 5, lane = t & 31;
    const unsigned fm = 0xffffffffu;
    const float* bW1 = W1 + (size_t)n * kE * kE;
    const float* bW2 = W2 + (size_t)n * kE * kE;
    int ck = 0;

    if (t == 0)
        for (int b = 0; b < NBUF; b++) mbar_init(mb_base + b * 8, 1);
    for (int i = t; i < kE * KOUT; i += 256)
        sW2T[(size_t)(i % KOUT) * kE + (i / KOUT)] = aW2[i];

    for (int tile = blockIdx.y; tile * TS < cnt; tile += gridDim.y) {
        const int m = min(TS, cnt - tile * TS);
        if (t < TS) {
            int id = (t < m) ? g_list[jin][n][tile * TS + t] : -1;
            sids[t]  = id;
            sdone[t] = (id >= 0) ? g_done[id] : 1;
        }
        __syncthreads();
        #pragma unroll
        for (int s = 0; s < TS; s++)
            sP0[t * SP + s] = (s < m) ? g_state[(size_t)sids[s] * kE + t] : 0.f;
        __syncthreads();
        {   // norms: warp wid -> sample wid
            float v = 0.f;
            #pragma unroll
            for (int q = 0; q < kE / 32; q++) {
                float x = sP0[(lane + 32 * q) * SP + wid];
                v = fmaf(x, x, v);
            }
            #pragma unroll
            for (int o = 16; o; o >>= 1) v += __shfl_down_sync(fm, v, o);
            if (lane == 0) snorm[wid] = sqrtf(v) + 1e-6f;
        }
        __syncthreads();
        {   // layer 1: sP0 -> relu -> sP1
            unsigned long long acc[4];
            layer_tma(sP0, bW1, b1[n * kE + t], sW, mb_base, t, ck, acc);
            #pragma unroll
            for (int p = 0; p < 4; p++) {
                float lo, hi; unpack2(acc[p], &lo, &hi);
                sP1[t * SP + 2 * p + 0] = fmaxf(lo, 0.f);
                sP1[t * SP + 2 * p + 1] = fmaxf(hi, 0.f);
            }
        }
        __syncthreads();
        {   // layer 2: sP1 -> relu/norm -> sP0 (+ commit g_state if active)
            unsigned long long acc[4];
            layer_tma(sP1, bW2, b2[n * kE + t], sW, mb_base, t, ck, acc);
            float o[TS];
            #pragma unroll
            for (int p = 0; p < 4; p++)
                unpack2(acc[p], &o[2 * p + 0], &o[2 * p + 1]);
            __syncthreads();   // norms + all sP0 reads complete
            #pragma unroll
            for (int s = 0; s < TS; s++) {
                float val = fmaxf(o[s], 0.f) / snorm[s];
                sP0[t * SP + s] = val;
                if (s < m && !sdone[s])
                    g_state[(size_t)sids[s] * kE + t] = val;
            }
        }
        __syncthreads();
        {   // layer 3: address hidden, sP0 -> relu -> sT (transposed)
            unsigned long long acc[4];
            layer_tma(sP0, aW1, ab1[t], sW, mb_base, t, ck, acc);
            #pragma unroll
            for (int p = 0; p < 4; p++) {
                float lo, hi; unpack2(acc[p], &lo, &hi);
                sT[(size_t)(2 * p + 0) * kE + t] = fmaxf(lo, 0.f);
                sT[(size_t)(2 * p + 1) * kE + t] = fmaxf(hi, 0.f);
            }
        }
        __syncthreads();

        if (wid < m) {
            const int b = sids[wid];
            int n_val = addr_head(sT, sW2T, ab2, wid, lane, b, k0, k1);
            if (lane == 0) {
                int done_pre = sdone[wid];
                int rn = done_pre ? n : n_val;   // frozen samples keep block n
                if (!done_pre && n_val == 0) g_done[b] = 1;
                int pos = atomicAdd(&g_cnt[jout][rn], 1);
                g_list[jout][rn][pos] = b;
            }
        }
        __syncthreads();
    }
}

// ---------------------------------------------------------------------------
// Fused final: block MLP + /norm + initial_state residual + out hidden + head.
// ---------------------------------------------------------------------------
__global__ void final_kernel(const float* __restrict__ W1,
                             const float* __restrict__ b1,
                             const float* __restrict__ W2,
                             const float* __restrict__ b2,
                             const float* __restrict__ oW1,
                             const float* __restrict__ ob1,
                             const float* __restrict__ oW2,
                             const float* __restrict__ ob2,
                             float* __restrict__ outp)
{
    const int n = blockIdx.x;
    const int cnt = g_cnt[kJ][n];
    if ((int)(blockIdx.y * TS) >= cnt) return;

    extern __shared__ float sm[];
    float* sP0  = sm + OFF_P0;
    float* sP1  = sm + OFF_P1;
    float* sW   = sm + OFF_W;
    float* sT   = sm + OFF_T;
    float* sW2T = sm + OFF_W2;   // [kC][kE]
    const uint32_t mb_base = smem_u32(sm + OFF_MB);
    __shared__ float snorm[TS];
    __shared__ int   sids[TS];
    const int t = threadIdx.x, wid = t >> 5, lane = t & 31;
    const unsigned fm = 0xffffffffu;
    const float* bW1 = W1 + (size_t)n * kE * kE;
    const float* bW2 = W2 + (size_t)n * kE * kE;
    int ck = 0;

    if (t == 0)
        for (int b = 0; b < NBUF; b++) mbar_init(mb_base + b * 8, 1);
    for (int i = t; i < kE * kC; i += 256)
        sW2T[(size_t)(i % kC) * kE + (i / kC)] = oW2[i];

    for (int tile = blockIdx.y; tile * TS < cnt; tile += gridDim.y) {
        const int m = min(TS, cnt - tile * TS);
        if (t < TS) sids[t] = (t < m) ? g_list[kJ][n][tile * TS + t] : -1;
        __syncthreads();
        #pragma unroll
        for (int s = 0; s < TS; s++)
            sP0[t * SP + s] = (s < m) ? g_state[(size_t)sids[s] * kE + t] : 0.f;
        __syncthreads();
        {
            float v = 0.f;
            #pragma unroll
            for (int q = 0; q < kE / 32; q++) {
                float x = sP0[(lane + 32 * q) * SP + wid];
                v = fmaf(x, x, v);
            }
            #pragma unroll
            for (int o = 16; o; o >>= 1) v += __shfl_down_sync(fm, v, o);
            if (lane == 0) snorm[wid] = sqrtf(v) + 1e-6f;
        }
        __syncthreads();
        {   // layer 1
            unsigned long long acc[4];
            layer_tma(sP0, bW1, b1[n * kE + t], sW, mb_base, t, ck, acc);
            #pragma unroll
            for (int p = 0; p < 4; p++) {
                float lo, hi; unpack2(acc[p], &lo, &hi);
                sP1[t * SP + 2 * p + 0] = fmaxf(lo, 0.f);
                sP1[t * SP + 2 * p + 1] = fmaxf(hi, 0.f);
            }
        }
        __syncthreads();
        {   // layer 2 + /norm + residual -> sP0
            unsigned long long acc[4];
            layer_tma(sP1, bW2, b2[n * kE + t], sW, mb_base, t, ck, acc);
            float o[TS];
            #pragma unroll
            for (int p = 0; p < 4; p++)
                unpack2(acc[p], &o[2 * p + 0], &o[2 * p + 1]);
            __syncthreads();
            #pragma unroll
            for (int s = 0; s < TS; s++) {
                float val = fmaxf(o[s], 0.f) / snorm[s];
                if (s < m) val += g_init[(size_t)sids[s] * kE + t];
                sP0[t * SP + s] = val;
            }
        }
        __syncthreads();
        {   // out hidden -> sT
            unsigned long long acc[4];
            layer_tma(sP0, oW1, ob1[t], sW, mb_base, t, ck, acc);
            #pragma unroll
            for (int p = 0; p < 4; p++) {
                float lo, hi; unpack2(acc[p], &lo, &hi);
                sT[(size_t)(2 * p + 0) * kE + t] = fmaxf(lo, 0.f);
                sT[(size_t)(2 * p + 1) * kE + t] = fmaxf(hi, 0.f);
            }
        }
        __syncthreads();

        if (wid < m) {
            const int b = sids[wid];
            float hr[kE / 32];
            #pragma unroll
            for (int q = 0; q < kE / 32; q++)
                hr[q] = sT[(size_t)wid * kE + lane + 32 * q];
            #pragma unroll
            for (int c = 0; c < kC; c++) {
                float sum = 0.f;
                #pragma unroll
                for (int q = 0; q < kE / 32; q++)
                    sum = fmaf(hr[q], sW2T[(size_t)c * kE + lane + 32 * q], sum);
                #pragma unroll
                for (int o = 16; o; o >>= 1) sum += __shfl_down_sync(fm, sum, o);
                if (lane == 0) outp[(size_t)b * kC + c] = sum + ob2[c];
            }
        }
        __syncthreads();
    }
}

// ---------------------------------------------------------------------------
// Launch: 7 kernels total
// ---------------------------------------------------------------------------
extern "C" void kernel_launch(void* const* d_in, const int* in_sizes, int n_in,
                              void* d_out, int out_size)
{
    (void)in_sizes; (void)n_in; (void)out_size;
    const float* x      = (const float*)d_in[0];
    const float* W_emb  = (const float*)d_in[1];
    const float* b_emb  = (const float*)d_in[2];
    const float* st_W1  = (const float*)d_in[3];
    const float* st_b1  = (const float*)d_in[4];
    const float* st_W2  = (const float*)d_in[5];
    const float* st_b2  = (const float*)d_in[6];
    const float* at0_W1 = (const float*)d_in[7];
    const float* at0_b1 = (const float*)d_in[8];
    const float* at0_W2 = (const float*)d_in[9];
    const float* at0_b2 = (const float*)d_in[10];
    const float* out_W1 = (const float*)d_in[11];
    const float* out_b1 = (const float*)d_in[12];
    const float* out_W2 = (const float*)d_in[13];
    const float* out_b2 = (const float*)d_in[14];
    float* out = (float*)d_out;

    // JAX keys: key_j = threefry((0,42), (0,j))  [fold_in(_GKEY, j)]
    uint32_t kk0[kJ + 1], kk1[kJ + 1];
    for (int j = 0; j <= kJ; j++)
        tf2x32(0u, 42u, 0u, (uint32_t)j, &kk0[j], &kk1[j]);

    float *p_state, *p_init;
    cudaGetSymbolAddress((void**)&p_state, g_state);
    cudaGetSymbolAddress((void**)&p_init,  g_init);

    cudaFuncSetAttribute(addr0_kernel,
        cudaFuncAttributeMaxDynamicSharedMemorySize, SMEM_BYTES);
    cudaFuncSetAttribute(jump_kernel,
        cudaFuncAttributeMaxDynamicSharedMemorySize, SMEM_BYTES);
    cudaFuncSetAttribute(final_kernel,
        cudaFuncAttributeMaxDynamicSharedMemorySize, SMEM_BYTES);

    // 1. embed (also zeroes routing counters for this replay)
    embed_kernel<<<dim3(kE / 64, kB / 32), 256>>>(x, W_emb, b_emb,
                                                  p_state, p_init, kB, kIN, kE);
    // 2. initial address
    addr0_kernel<<<kB / TS, 256, SMEM_BYTES>>>(at0_W1, at0_b1, at0_W2, at0_b2,
                                               kk0[0], kk1[0]);
    // 3-6. fused jumps
    for (int i = 0; i < kJ; i++)
        jump_kernel<<<dim3(kNB, 16), 256, SMEM_BYTES>>>(
            st_W1, st_b1, st_W2, st_b2,
            at0_W1, at0_b1, at0_W2, at0_b2,
            kk0[i + 1], kk1[i + 1], i, i + 1);
    // 7. fused final block step + output head
    final_kernel<<<dim3(kNB, 16), 256, SMEM_BYTES>>>(
        st_W1, st_b1, st_W2, st_b2,
        out_W1, out_b1, out_W2, out_b2, out);
}

// round 13
// speedup vs baseline: 2.4999x; 1.5544x over previous
#include <cuda_runtime.h>
#include <stdint.h>

// ---------------------------------------------------------------------------
// Problem constants
// ---------------------------------------------------------------------------
static const int kB  = 1024;   // batch
static const int kIN = 784;    // input dim
static const int kE  = 256;    // embed dim
static const int kC  = 10;     // classes
static const int kAD = 3;      // ADIM
static const int kBR = 4;      // BRAIN
static const int kNB = 64;     // blocks
static const int kJ  = 4;      // NJUMPS
static const int TS  = 4;      // samples per tile (small => many independent CTAs)
static const int SP  = 4;      // interleaved activation row stride (16B rows)
static const int KOUT = kAD * kBR;  // 12
static const int GY  = 32;     // y-grid (tiles in flight per block)

// TMA-staged weight pipeline: ring of 2 x 32KB buffers, depth-1 prefetch
static const int CH   = 32;          // e-rows per chunk
static const int NCH  = kE / CH;     // 8 chunks per layer
static const int NBUF = 2;           // ring buffers
static const int WBUF = CH * kE;     // 8192 floats per buffer
static const int WBYTES = WBUF * 4;  // 32768 bytes

// dynamic smem layout (floats) -- total ~90KB => 2 CTAs/SM
static const int OFF_P0 = 0;                        // kE*SP = 1024
static const int OFF_P1 = kE * SP;                  // 1024
static const int OFF_W  = 2 * kE * SP;              // 2048 .. +16384
static const int OFF_T  = OFF_W + NBUF * WBUF;      // 18432 (TS*kE = 1024)
static const int OFF_W2 = OFF_T + TS * kE;          // 19456 (KOUT*kE = 3072)
static const int OFF_MB = OFF_W2 + KOUT * kE;       // 22528 (mbarriers)
static const int SMEM_FLOATS = OFF_MB + 8;          // 22536
static const int SMEM_BYTES  = SMEM_FLOATS * 4;     // 90144

// ---------------------------------------------------------------------------
// Scratch (device globals -- no cudaMalloc allowed)
// ---------------------------------------------------------------------------
__device__ float g_state[kB * kE];
__device__ float g_init [kB * kE];
__device__ int   g_done [kB];
__device__ int   g_cnt  [kJ + 1][kNB];
__device__ int   g_list [kJ + 1][kNB][kB];

// ---------------------------------------------------------------------------
// Threefry-2x32-20 (KAT: key(0,0) ctr(0,0) -> 0x6b200159, 0x99ba4efe)
// ---------------------------------------------------------------------------
__host__ __device__ inline void tf2x32(uint32_t k0, uint32_t k1,
                                       uint32_t x0, uint32_t x1,
                                       uint32_t* o0, uint32_t* o1)
{
    uint32_t ks2 = k0 ^ k1 ^ 0x1BD11BDAu;
    x0 += k0; x1 += k1;
#define TF_ROT(v, d) (((v) << (d)) | ((v) >> (32 - (d))))
#define TF_R4(a, b, c, d)                                    \
    { x0 += x1; x1 = TF_ROT(x1, a); x1 ^= x0;                \
      x0 += x1; x1 = TF_ROT(x1, b); x1 ^= x0;                \
      x0 += x1; x1 = TF_ROT(x1, c); x1 ^= x0;                \
      x0 += x1; x1 = TF_ROT(x1, d); x1 ^= x0; }
    TF_R4(13, 15, 26, 6)   x0 += k1;  x1 += ks2 + 1u;
    TF_R4(17, 29, 16, 24)  x0 += ks2; x1 += k0  + 2u;
    TF_R4(13, 15, 26, 6)   x0 += k0;  x1 += k1  + 3u;
    TF_R4(17, 29, 16, 24)  x0 += k1;  x1 += ks2 + 4u;
    TF_R4(13, 15, 26, 6)   x0 += ks2; x1 += k0  + 5u;
#undef TF_R4
#undef TF_ROT
    *o0 = x0; *o1 = x1;
}

// exact JAX gumbel (jax_threefry_partitionable): bits = o0^o1 of tf(key,(0,idx))
__device__ __forceinline__ float gumbel_exact(uint32_t k0, uint32_t k1, uint32_t idx)
{
    uint32_t y0, y1;
    tf2x32(k0, k1, 0u, idx, &y0, &y1);
    uint32_t bits = y0 ^ y1;
    float u = __uint_as_float((bits >> 9) | 0x3f800000u) - 1.0f;
    const float minv = 1e-6f;
    const float span = 0.999999f - 1e-6f;
    float vv = fmaxf(minv, u * span + minv);
    return (float)(-log(-log((double)vv)));  // fp64: immune to fast-math logf
}

// ---------------------------------------------------------------------------
// Packed f32x2 helpers
// ---------------------------------------------------------------------------
#define FMA2(acc, a, b) \
    asm("fma.rn.f32x2 %0, %1, %2, %0;" : "+l"(acc) : "l"(a), "l"(b))

__device__ __forceinline__ unsigned long long pack2(float lo, float hi)
{
    unsigned long long p;
    unsigned int l = __float_as_uint(lo), h = __float_as_uint(hi);
    asm("mov.b64 %0, {%1, %2};" : "=l"(p) : "r"(l), "r"(h));
    return p;
}
__device__ __forceinline__ void unpack2(unsigned long long p, float* lo, float* hi)
{
    unsigned int l, h;
    asm("mov.b64 {%0, %1}, %2;" : "=r"(l), "=r"(h) : "l"(p));
    *lo = __uint_as_float(l); *hi = __uint_as_float(h);
}

// ---------------------------------------------------------------------------
// TMA bulk + mbarrier helpers
// ---------------------------------------------------------------------------
__device__ __forceinline__ uint32_t smem_u32(const void* p)
{
    return (uint32_t)__cvta_generic_to_shared(p);
}

__device__ __forceinline__ void mbar_init(uint32_t mbar, uint32_t count)
{
    asm volatile("mbarrier.init.shared.b64 [%0], %1;"
                 :: "r"(mbar), "r"(count) : "memory");
}

__device__ __forceinline__ void mbar_expect_tx(uint32_t mbar, uint32_t bytes)
{
    asm volatile("mbarrier.arrive.expect_tx.shared.b64 _, [%0], %1;"
                 :: "r"(mbar), "r"(bytes) : "memory");
}

__device__ __forceinline__ void mbar_wait(uint32_t mbar, uint32_t parity)
{
    asm volatile(
        "{\n\t"
        ".reg .pred P1;\n\t"
        "WAIT_LOOP_%=:\n\t"
        "mbarrier.try_wait.parity.acquire.cta.shared::cta.b64 P1, [%0], %1, 0x989680;\n\t"
        "@P1 bra.uni WAIT_DONE_%=;\n\t"
        "bra.uni WAIT_LOOP_%=;\n\t"
        "WAIT_DONE_%=:\n\t"
        "}"
        :: "r"(mbar), "r"(parity) : "memory");
}

__device__ __forceinline__ void tma_bulk(uint32_t dst_smem, const float* gsrc,
                                         uint32_t bytes, uint32_t mbar)
{
    asm volatile(
        "cp.async.bulk.shared::cluster.global.mbarrier::complete_tx::bytes "
        "[%0], [%1], %2, [%3];"
        :: "r"(dst_smem), "l"(gsrc), "r"(bytes), "r"(mbar) : "memory");
}

__device__ __forceinline__ void issue_chunk_tma(float* sW, uint32_t mb_base,
                                                const float* gW, int local_c,
                                                int idx, int tid)
{
    if (tid == 0) {
        uint32_t mbar = mb_base + (uint32_t)(idx & 1) * 8;
        uint32_t dst  = smem_u32(sW + (size_t)(idx & 1) * WBUF);
        mbar_expect_tx(mbar, WBYTES);
        tma_bulk(dst, gW + (size_t)local_c * WBUF, WBYTES, mbar);
    }
}

// ---------------------------------------------------------------------------
// One dense layer over 4 samples, weights TMA staged through a 2-ring:
//   acc pair p = samples (2p,2p+1): acc += W[e][t]*in[e][s], e ascending
//   (identical per-sample scalar-FMA order -> bit-identical routing).
// ck: running chunk counter (advances by NCH per layer).
// WAR: issue(c+1) into buf (c+1)&1 happens after barrier proving all threads
// finished compute(c-1), the last reader of that buffer.
// parity for buffer b at use idx: ((idx>>1)&1) alternates per reuse.
// ---------------------------------------------------------------------------
__device__ __forceinline__ void layer_tma(const float* sIn,
                                          const float* __restrict__ gW,
                                          float bv, float* sW, uint32_t mb_base,
                                          int t, int& ck,
                                          unsigned long long* acc)
{
    acc[0] = pack2(bv, bv);
    acc[1] = pack2(bv, bv);

    issue_chunk_tma(sW, mb_base, gW, 0, ck + 0, t);
    #pragma unroll 1
    for (int c = 0; c < NCH; c++) {
        __syncthreads();            // all threads finished compute(c-1)
        if (c + 1 < NCH)
            issue_chunk_tma(sW, mb_base, gW, c + 1, ck + c + 1, t);
        {
            int idx = ck + c;
            mbar_wait(mb_base + (uint32_t)(idx & 1) * 8,
                      (uint32_t)((idx >> 1) & 1));
        }
        const float* wb = sW + (size_t)((ck + c) & 1) * WBUF + t;
        const float* ab = sIn + (size_t)(c * CH) * SP;
        #pragma unroll
        for (int e = 0; e < CH; e++) {
            float w = wb[e * kE];
            unsigned long long wp = pack2(w, w);
            ulonglong2 a03 = *(const ulonglong2*)(ab + e * SP);
            FMA2(acc[0], a03.x, wp);
            FMA2(acc[1], a03.y, wp);
        }
    }
    ck += NCH;
}

// ---------------------------------------------------------------------------
// Embed GEMM: C = A[MxK] @ W[KxN] + bias, copy to C2. Also zeroes g_cnt.
// ---------------------------------------------------------------------------
__global__ void embed_kernel(const float* __restrict__ A,
                             const float* __restrict__ W,
                             const float* __restrict__ bias,
                             float* __restrict__ C,
                             float* __restrict__ C2,
                             int M, int K, int Nn)
{
    const int t = threadIdx.x;
    if (blockIdx.x == 0 && blockIdx.y == 0) {
        int* c = &g_cnt[0][0];
        for (int i = t; i < (kJ + 1) * kNB; i += 256) c[i] = 0;
    }
    __shared__ float As[16][33];
    __shared__ float Ws[16][64];
    const int tx = t & 15;
    const int ty = t >> 4;
    const int row0 = blockIdx.y * 32;
    const int col0 = blockIdx.x * 64;
    float acc[2][4] = {{0.f,0.f,0.f,0.f},{0.f,0.f,0.f,0.f}};

    for (int k0 = 0; k0 < K; k0 += 16) {
        if (t < 128) {
            int r  = t >> 2;
            int kk = (t & 3) * 4;
            float4 v = *(const float4*)(A + (size_t)(row0 + r) * K + k0 + kk);
            As[kk + 0][r] = v.x; As[kk + 1][r] = v.y;
            As[kk + 2][r] = v.z; As[kk + 3][r] = v.w;
        }
        {
            int kk = t >> 4;
            int c  = (t & 15) * 4;
            *(float4*)&Ws[kk][c] =
                *(const float4*)(W + (size_t)(k0 + kk) * Nn + col0 + c);
        }
        __syncthreads();
        #pragma unroll
        for (int kk = 0; kk < 16; kk++) {
            float a0 = As[kk][ty * 2 + 0];
            float a1 = As[kk][ty * 2 + 1];
            float4 b4 = *(const float4*)&Ws[kk][tx * 4];
            acc[0][0] = fmaf(a0, b4.x, acc[0][0]);
            acc[0][1] = fmaf(a0, b4.y, acc[0][1]);
            acc[0][2] = fmaf(a0, b4.z, acc[0][2]);
            acc[0][3] = fmaf(a0, b4.w, acc[0][3]);
            acc[1][0] = fmaf(a1, b4.x, acc[1][0]);
            acc[1][1] = fmaf(a1, b4.y, acc[1][1]);
            acc[1][2] = fmaf(a1, b4.z, acc[1][2]);
            acc[1][3] = fmaf(a1, b4.w, acc[1][3]);
        }
        __syncthreads();
    }

    float4 bv = *(const float4*)(bias + col0 + tx * 4);
    #pragma unroll
    for (int i = 0; i < 2; i++) {
        float4 o;
        o.x = acc[i][0] + bv.x; o.y = acc[i][1] + bv.y;
        o.z = acc[i][2] + bv.z; o.w = acc[i][3] + bv.w;
        size_t off = (size_t)(row0 + ty * 2 + i) * Nn + col0 + tx * 4;
        *(float4*)(C + off)  = o;
        *(float4*)(C2 + off) = o;
    }
}

// ---------------------------------------------------------------------------
// Shared epilogue: logits + gumbel + argmax for one sample per warp.
// ---------------------------------------------------------------------------
__device__ __forceinline__ int addr_head(const float* sT, const float* sW2T,
                                         const float* __restrict__ ab2,
                                         int s, int lane, int b,
                                         uint32_t k0, uint32_t k1)
{
    const unsigned fm = 0xffffffffu;
    float hr[kE / 32];
    #pragma unroll
    for (int q = 0; q < kE / 32; q++)
        hr[q] = sT[(size_t)s * kE + lane + 32 * q];
    float zmine = 0.f;
    #pragma unroll
    for (int k = 0; k < KOUT; k++) {
        float sum = 0.f;
        #pragma unroll
        for (int q = 0; q < kE / 32; q++)
            sum = fmaf(hr[q], sW2T[(size_t)k * kE + lane + 32 * q], sum);
        #pragma unroll
        for (int o = 16; o; o >>= 1) sum += __shfl_down_sync(fm, sum, o);
        float v = __shfl_sync(fm, sum, 0);
        if (lane == k) zmine = v + ab2[k];
    }
    if (lane < KOUT) zmine += gumbel_exact(k0, k1, (uint32_t)(b * KOUT + lane));
    float zv[KOUT];
    #pragma unroll
    for (int k = 0; k < KOUT; k++) zv[k] = __shfl_sync(fm, zmine, k);

    int n_val = 0;
    if (lane == 0) {
        #pragma unroll
        for (int d = 0; d < kAD; d++) {
            int bi = 0; float bvv = zv[d * kBR];
            #pragma unroll
            for (int c = 1; c < kBR; c++) {
                float x = zv[d * kBR + c];
                if (x > bvv) { bvv = x; bi = c; }
            }
            n_val = n_val * kBR + bi;
        }
    }
    return n_val;
}

// ---------------------------------------------------------------------------
// addr0: h = relu(state @ aW1 + ab1); logits (+gumbel key0); route list[0].
// 256 CTAs x 256 threads, 4 samples each.
// ---------------------------------------------------------------------------
__global__ void addr0_kernel(const float* __restrict__ aW1,
                             const float* __restrict__ ab1,
                             const float* __restrict__ aW2,
                             const float* __restrict__ ab2,
                             uint32_t k0, uint32_t k1)
{
    extern __shared__ float sm[];
    float* sP0  = sm + OFF_P0;
    float* sW   = sm + OFF_W;
    float* sT   = sm + OFF_T;
    float* sW2T = sm + OFF_W2;
    const uint32_t mb_base = smem_u32(sm + OFF_MB);
    const int t = threadIdx.x, wid = t >> 5, lane = t & 31;
    const int b0 = blockIdx.x * TS;
    int ck = 0;

    if (t == 0)
        for (int b = 0; b < NBUF; b++) mbar_init(mb_base + b * 8, 1);
    for (int i = t; i < kE * KOUT; i += 256)
        sW2T[(size_t)(i % KOUT) * kE + (i / KOUT)] = aW2[i];
    #pragma unroll
    for (int s = 0; s < TS; s++)
        sP0[t * SP + s] = g_state[(size_t)(b0 + s) * kE + t];
    __syncthreads();

    {
        unsigned long long acc[2];
        layer_tma(sP0, aW1, ab1[t], sW, mb_base, t, ck, acc);
        #pragma unroll
        for (int p = 0; p < 2; p++) {
            float lo, hi; unpack2(acc[p], &lo, &hi);
            sT[(size_t)(2 * p + 0) * kE + t] = fmaxf(lo, 0.f);
            sT[(size_t)(2 * p + 1) * kE + t] = fmaxf(hi, 0.f);
        }
    }
    __syncthreads();

    if (wid < TS) {
        const int b = b0 + wid;
        int n_val = addr_head(sT, sW2T, ab2, wid, lane, b, k0, k1);
        if (lane == 0) {
            g_done[b] = 0;
            int pos = atomicAdd(&g_cnt[0][n_val], 1);
            g_list[0][n_val][pos] = b;
        }
    }
}

// ---------------------------------------------------------------------------
// Fused jump (TMA weight ring, 4 samples/tile): consume list[jin].
// ---------------------------------------------------------------------------
__global__ void jump_kernel(const float* __restrict__ W1,
                            const float* __restrict__ b1,
                            const float* __restrict__ W2,
                            const float* __restrict__ b2,
                            const float* __restrict__ aW1,
                            const float* __restrict__ ab1,
                            const float* __restrict__ aW2,
                            const float* __restrict__ ab2,
                            uint32_t k0, uint32_t k1, int jin, int jout)
{
    const int n = blockIdx.x;
    const int cnt = g_cnt[jin][n];
    if ((int)(blockIdx.y * TS) >= cnt) return;

    extern __shared__ float sm[];
    float* sP0  = sm + OFF_P0;
    float* sP1  = sm + OFF_P1;
    float* sW   = sm + OFF_W;
    float* sT   = sm + OFF_T;
    float* sW2T = sm + OFF_W2;
    const uint32_t mb_base = smem_u32(sm + OFF_MB);
    __shared__ float snorm[TS];
    __shared__ int   sids[TS];
    __shared__ int   sdone[TS];
    const int t = threadIdx.x, wid = t >> 5, lane = t & 31;
    const unsigned fm = 0xffffffffu;
    const float* bW1 = W1 + (size_t)n * kE * kE;
    const float* bW2 = W2 + (size_t)n * kE * kE;
    int ck = 0;

    if (t == 0)
        for (int b = 0; b < NBUF; b++) mbar_init(mb_base + b * 8, 1);
    for (int i = t; i < kE * KOUT; i += 256)
        sW2T[(size_t)(i % KOUT) * kE + (i / KOUT)] = aW2[i];

    for (int tile = blockIdx.y; tile * TS < cnt; tile += gridDim.y) {
        const int m = min(TS, cnt - tile * TS);
        if (t < TS) {
            int id = (t < m) ? g_list[jin][n][tile * TS + t] : -1;
            sids[t]  = id;
            sdone[t] = (id >= 0) ? g_done[id] : 1;
        }
        __syncthreads();
        #pragma unroll
        for (int s = 0; s < TS; s++)
            sP0[t * SP + s] = (s < m) ? g_state[(size_t)sids[s] * kE + t] : 0.f;
        __syncthreads();
        if (wid < TS) {   // norms: warp wid -> sample wid
            float v = 0.f;
            #pragma unroll
            for (int q = 0; q < kE / 32; q++) {
                float x = sP0[(lane + 32 * q) * SP + wid];
                v = fmaf(x, x, v);
            }
            #pragma unroll
            for (int o = 16; o; o >>= 1) v += __shfl_down_sync(fm, v, o);
            if (lane == 0) snorm[wid] = sqrtf(v) + 1e-6f;
        }
        __syncthreads();
        {   // layer 1: sP0 -> relu -> sP1
            unsigned long long acc[2];
            layer_tma(sP0, bW1, b1[n * kE + t], sW, mb_base, t, ck, acc);
            #pragma unroll
            for (int p = 0; p < 2; p++) {
                float lo, hi; unpack2(acc[p], &lo, &hi);
                sP1[t * SP + 2 * p + 0] = fmaxf(lo, 0.f);
                sP1[t * SP + 2 * p + 1] = fmaxf(hi, 0.f);
            }
        }
        __syncthreads();
        {   // layer 2: sP1 -> relu/norm -> sP0 (+ commit g_state if active)
            unsigned long long acc[2];
            layer_tma(sP1, bW2, b2[n * kE + t], sW, mb_base, t, ck, acc);
            float o[TS];
            #pragma unroll
            for (int p = 0; p < 2; p++)
                unpack2(acc[p], &o[2 * p + 0], &o[2 * p + 1]);
            __syncthreads();   // norms + all sP0 reads complete
            #pragma unroll
            for (int s = 0; s < TS; s++) {
                float val = fmaxf(o[s], 0.f) / snorm[s];
                sP0[t * SP + s] = val;
                if (s < m && !sdone[s])
                    g_state[(size_t)sids[s] * kE + t] = val;
            }
        }
        __syncthreads();
        {   // layer 3: address hidden, sP0 -> relu -> sT (transposed)
            unsigned long long acc[2];
            layer_tma(sP0, aW1, ab1[t], sW, mb_base, t, ck, acc);
            #pragma unroll
            for (int p = 0; p < 2; p++) {
                float lo, hi; unpack2(acc[p], &lo, &hi);
                sT[(size_t)(2 * p + 0) * kE + t] = fmaxf(lo, 0.f);
                sT[(size_t)(2 * p + 1) * kE + t] = fmaxf(hi, 0.f);
            }
        }
        __syncthreads();

        if (wid < m) {
            const int b = sids[wid];
            int n_val = addr_head(sT, sW2T, ab2, wid, lane, b, k0, k1);
            if (lane == 0) {
                int done_pre = sdone[wid];
                int rn = done_pre ? n : n_val;   // frozen samples keep block n
                if (!done_pre && n_val == 0) g_done[b] = 1;
                int pos = atomicAdd(&g_cnt[jout][rn], 1);
                g_list[jout][rn][pos] = b;
            }
        }
        __syncthreads();
    }
}

// ---------------------------------------------------------------------------
// Fused final: block MLP + /norm + initial_state residual + out hidden + head.
// ---------------------------------------------------------------------------
__global__ void final_kernel(const float* __restrict__ W1,
                             const float* __restrict__ b1,
                             const float* __restrict__ W2,
                             const float* __restrict__ b2,
                             const float* __restrict__ oW1,
                             const float* __restrict__ ob1,
                             const float* __restrict__ oW2,
                             const float* __restrict__ ob2,
                             float* __restrict__ outp)
{
    const int n = blockIdx.x;
    const int cnt = g_cnt[kJ][n];
    if ((int)(blockIdx.y * TS) >= cnt) return;

    extern __shared__ float sm[];
    float* sP0  = sm + OFF_P0;
    float* sP1  = sm + OFF_P1;
    float* sW   = sm + OFF_W;
    float* sT   = sm + OFF_T;
    float* sW2T = sm + OFF_W2;   // [kC][kE]
    const uint32_t mb_base = smem_u32(sm + OFF_MB);
    __shared__ float snorm[TS];
    __shared__ int   sids[TS];
    const int t = threadIdx.x, wid = t >> 5, lane = t & 31;
    const unsigned fm = 0xffffffffu;
    const float* bW1 = W1 + (size_t)n * kE * kE;
    const float* bW2 = W2 + (size_t)n * kE * kE;
    int ck = 0;

    if (t == 0)
        for (int b = 0; b < NBUF; b++) mbar_init(mb_base + b * 8, 1);
    for (int i = t; i < kE * kC; i += 256)
        sW2T[(size_t)(i % kC) * kE + (i / kC)] = oW2[i];

    for (int tile = blockIdx.y; tile * TS < cnt; tile += gridDim.y) {
        const int m = min(TS, cnt - tile * TS);
        if (t < TS) sids[t] = (t < m) ? g_list[kJ][n][tile * TS + t] : -1;
        __syncthreads();
        #pragma unroll
        for (int s = 0; s < TS; s++)
            sP0[t * SP + s] = (s < m) ? g_state[(size_t)sids[s] * kE + t] : 0.f;
        __syncthreads();
        if (wid < TS) {
            float v = 0.f;
            #pragma unroll
            for (int q = 0; q < kE / 32; q++) {
                float x = sP0[(lane + 32 * q) * SP + wid];
                v = fmaf(x, x, v);
            }
            #pragma unroll
            for (int o = 16; o; o >>= 1) v += __shfl_down_sync(fm, v, o);
            if (lane == 0) snorm[wid] = sqrtf(v) + 1e-6f;
        }
        __syncthreads();
        {   // layer 1
            unsigned long long acc[2];
            layer_tma(sP0, bW1, b1[n * kE + t], sW, mb_base, t, ck, acc);
            #pragma unroll
            for (int p = 0; p < 2; p++) {
                float lo, hi; unpack2(acc[p], &lo, &hi);
                sP1[t * SP + 2 * p + 0] = fmaxf(lo, 0.f);
                sP1[t * SP + 2 * p + 1] = fmaxf(hi, 0.f);
            }
        }
        __syncthreads();
        {   // layer 2 + /norm + residual -> sP0
            unsigned long long acc[2];
            layer_tma(sP1, bW2, b2[n * kE + t], sW, mb_base, t, ck, acc);
            float o[TS];
            #pragma unroll
            for (int p = 0; p < 2; p++)
                unpack2(acc[p], &o[2 * p + 0], &o[2 * p + 1]);
            __syncthreads();
            #pragma unroll
            for (int s = 0; s < TS; s++) {
                float val = fmaxf(o[s], 0.f) / snorm[s];
                if (s < m) val += g_init[(size_t)sids[s] * kE + t];
                sP0[t * SP + s] = val;
            }
        }
        __syncthreads();
        {   // out hidden -> sT
            unsigned long long acc[2];
            layer_tma(sP0, oW1, ob1[t], sW, mb_base, t, ck, acc);
            #pragma unroll
            for (int p = 0; p < 2; p++) {
                float lo, hi; unpack2(acc[p], &lo, &hi);
                sT[(size_t)(2 * p + 0) * kE + t] = fmaxf(lo, 0.f);
                sT[(size_t)(2 * p + 1) * kE + t] = fmaxf(hi, 0.f);
            }
        }
        __syncthreads();

        if (wid < m) {
            const int b = sids[wid];
            float hr[kE / 32];
            #pragma unroll
            for (int q = 0; q < kE / 32; q++)
                hr[q] = sT[(size_t)wid * kE + lane + 32 * q];
            #pragma unroll
            for (int c = 0; c < kC; c++) {
                float sum = 0.f;
                #pragma unroll
                for (int q = 0; q < kE / 32; q++)
                    sum = fmaf(hr[q], sW2T[(size_t)c * kE + lane + 32 * q], sum);
                #pragma unroll
                for (int o = 16; o; o >>= 1) sum += __shfl_down_sync(fm, sum, o);
                if (lane == 0) outp[(size_t)b * kC + c] = sum + ob2[c];
            }
        }
        __syncthreads();
    }
}

// ---------------------------------------------------------------------------
// Launch: 7 kernels total
// ---------------------------------------------------------------------------
extern "C" void kernel_launch(void* const* d_in, const int* in_sizes, int n_in,
                              void* d_out, int out_size)
{
    (void)in_sizes; (void)n_in; (void)out_size;
    const float* x      = (const float*)d_in[0];
    const float* W_emb  = (const float*)d_in[1];
    const float* b_emb  = (const float*)d_in[2];
    const float* st_W1  = (const float*)d_in[3];
    const float* st_b1  = (const float*)d_in[4];
    const float* st_W2  = (const float*)d_in[5];
    const float* st_b2  = (const float*)d_in[6];
    const float* at0_W1 = (const float*)d_in[7];
    const float* at0_b1 = (const float*)d_in[8];
    const float* at0_W2 = (const float*)d_in[9];
    const float* at0_b2 = (const float*)d_in[10];
    const float* out_W1 = (const float*)d_in[11];
    const float* out_b1 = (const float*)d_in[12];
    const float* out_W2 = (const float*)d_in[13];
    const float* out_b2 = (const float*)d_in[14];
    float* out = (float*)d_out;

    // JAX keys: key_j = threefry((0,42), (0,j))  [fold_in(_GKEY, j)]
    uint32_t kk0[kJ + 1], kk1[kJ + 1];
    for (int j = 0; j <= kJ; j++)
        tf2x32(0u, 42u, 0u, (uint32_t)j, &kk0[j], &kk1[j]);

    float *p_state, *p_init;
    cudaGetSymbolAddress((void**)&p_state, g_state);
    cudaGetSymbolAddress((void**)&p_init,  g_init);

    cudaFuncSetAttribute(addr0_kernel,
        cudaFuncAttributeMaxDynamicSharedMemorySize, SMEM_BYTES);
    cudaFuncSetAttribute(jump_kernel,
        cudaFuncAttributeMaxDynamicSharedMemorySize, SMEM_BYTES);
    cudaFuncSetAttribute(final_kernel,
        cudaFuncAttributeMaxDynamicSharedMemorySize, SMEM_BYTES);

    // 1. embed (also zeroes routing counters for this replay)
    embed_kernel<<<dim3(kE / 64, kB / 32), 256>>>(x, W_emb, b_emb,
                                                  p_state, p_init, kB, kIN, kE);
    // 2. initial address
    addr0_kernel<<<kB / TS, 256, SMEM_BYTES>>>(at0_W1, at0_b1, at0_W2, at0_b2,
                                               kk0[0], kk1[0]);
    // 3-6. fused jumps
    for (int i = 0; i < kJ; i++)
        jump_kernel<<<dim3(kNB, GY), 256, SMEM_BYTES>>>(
            st_W1, st_b1, st_W2, st_b2,
            at0_W1, at0_b1, at0_W2, at0_b2,
            kk0[i + 1], kk1[i + 1], i, i + 1);
    // 7. fused final block step + output head
    final_kernel<<<dim3(kNB, GY), 256, SMEM_BYTES>>>(
        st_W1, st_b1, st_W2, st_b2,
        out_W1, out_b1, out_W2, out_b2, out);
}